// round 16
// baseline (speedup 1.0000x reference)
#include <cuda_runtime.h>
#include <cuda_fp16.h>
#include <cstdint>

// DeconvCapsuleLayer, round 16: M=128 tiles / 512 threads / 16 warps per block,
// 96KB smem (B 32K | A 32K | D 32K) -> 2 blocks/SM = 32 warps/SM (was 24) and
// half the barrier rendezvous per pixel. Same single-term fp16 mma.sync GEMM,
// half2 D staging, register routing -- numerics identical to round 13/15.
//
// Reference quirk reproduced: route i of output batch b uses input
// (bb, cin) = ((8b+i)&3, (8b+i)>>2).

namespace {
constexpr int HIN = 56, WIN = 56, CIN = 8, AIN = 32;
constexpr int HP = 112, WP = 112;
constexpr int XN = 4 * 56 * 56 * 8 * 32;     // elements in x
constexpr int BN = 4 * 128 * 128;            // elements in B (hi only)
// SMEM map: B 32KB | A 32KB (128 rows x 256B) | D 32KB (128 rows x 256B)
constexpr int SM_B = 0;
constexpr int SM_A = 32768;
constexpr int SM_D = 65536;
constexpr int SMEM_TOTAL = 98304;
constexpr int NBLK = 74;                     // blocks per class (296 = 148*2)
}

// Pre-swizzled B_hi: [cls(4)][n(128)][k(128)] fp16.
__device__ __half g_B[BN];
// fp16 hi of x: [bb][ii][jj][cin][ain]
__device__ __half g_xh[XN];

__global__ void __launch_bounds__(256)
prep_kernel(const float* __restrict__ W, const float* __restrict__ x) {
    int idx = blockIdx.x * blockDim.x + threadIdx.x;

    // ---- x: 8 elements per thread, coalesced float4 loads -> uint4 store
    if (idx < XN / 8) {
        const float4* xs = (const float4*)x + idx * 2;
        float4 v0 = xs[0];
        float4 v1 = xs[1];
        __half2 h0 = __floats2half2_rn(v0.x, v0.y);
        __half2 h1 = __floats2half2_rn(v0.z, v0.w);
        __half2 h2 = __floats2half2_rn(v1.x, v1.y);
        __half2 h3 = __floats2half2_rn(v1.z, v1.w);
        uint4 pk = make_uint4(*(uint32_t*)&h0, *(uint32_t*)&h1,
                              *(uint32_t*)&h2, *(uint32_t*)&h3);
        ((uint4*)g_xh)[idx] = pk;
    }

    // ---- B: one element per thread (small: 64K)
    if (idx < BN) {
        int k   = idx & 127;
        int n   = (idx >> 7) & 127;
        int cls = idx >> 14;
        int t = k >> 5, ain = k & 31;
        int hpar = cls >> 1, wpar = cls & 1;
        int p = (1 - hpar) + 2 * (t >> 1);
        int q = (1 - wpar) + 2 * (t & 1);
        float wv = W[((p * 4 + q) * 128 + n) * AIN + ain];
        uint32_t off = (uint32_t)(n * 256)
                     + (((uint32_t)(k * 2)) ^ ((uint32_t)(n & 7) << 4));
        *(__half*)((char*)g_B + (((size_t)cls) << 15) + off) = __float2half_rn(wv);
    }
}

// ---------------- PTX helpers ----------------
__device__ __forceinline__ void cpa16(uint32_t dst, const void* src, uint32_t srcsize) {
    asm volatile("cp.async.cg.shared.global [%0], [%1], 16, %2;"
                 :: "r"(dst), "l"(src), "r"(srcsize) : "memory");
}
__device__ __forceinline__ void cpa_commit() {
    asm volatile("cp.async.commit_group;" ::: "memory");
}
__device__ __forceinline__ void ldm_x4(uint32_t* r, uint32_t addr) {
    asm volatile("ldmatrix.sync.aligned.m8n8.x4.shared.b16 {%0,%1,%2,%3}, [%4];"
                 : "=r"(r[0]), "=r"(r[1]), "=r"(r[2]), "=r"(r[3]) : "r"(addr));
}
__device__ __forceinline__ void mma_f16(float* d, const uint32_t* a, const uint32_t* b) {
    asm volatile("mma.sync.aligned.m16n8k16.row.col.f32.f16.f16.f32 "
                 "{%0,%1,%2,%3}, {%4,%5,%6,%7}, {%8,%9}, {%0,%1,%2,%3};"
                 : "+f"(d[0]), "+f"(d[1]), "+f"(d[2]), "+f"(d[3])
                 : "r"(a[0]), "r"(a[1]), "r"(a[2]), "r"(a[3]), "r"(b[0]), "r"(b[1]));
}
__device__ __forceinline__ uint32_t pack_h2(float a, float b) {
    __half2 h = __floats2half2_rn(a, b);
    return *(uint32_t*)&h;
}

__global__ void __launch_bounds__(512, 2)
deconv_caps_pers_kernel(const float* __restrict__ bias,
                        float* __restrict__ out)
{
    extern __shared__ char smem[];
    const uint32_t sbase = (uint32_t)__cvta_generic_to_shared(smem);
    const int tid  = threadIdx.x;
    const int lane = tid & 31;
    const int wid  = tid >> 5;               // 0..15
    const int cls  = blockIdx.y;
    const int blk  = blockIdx.x;
    const int hpar = cls >> 1, wpar = cls & 1;

    // tile range: 784 16-pixel tiles over 74 blocks -> first 44 get 11, rest 10
    const int base = blk * 10 + (blk < 44 ? blk : 44);
    const int cnt  = 10 + (blk < 44 ? 1 : 0);

    // ---- issue B copy (pre-swizzled, 32KB) via cp.async
    {
        const char* Bsrc = (const char*)g_B + ((size_t)cls << 15);
        #pragma unroll
        for (int i = 0; i < 4; ++i) {
            uint32_t o = (uint32_t)(tid + 512 * i) * 16;
            cpa16(sbase + SM_B + o, Bsrc + o, 16);
        }
        cpa_commit();
    }

    // ---- per-thread gather constants: row m = tid>>2 (0..127), tap = tid&3
    const int m = tid >> 2, mytap = tid & 3;
    const int mypix = m >> 3, route = m & 7;   // pixel 0..15 within tile
    const uint32_t rx_m = (uint32_t)(m & 7) << 4;

    auto gather = [&](int T) {
        const int P   = T * 16 + mypix;
        const int b   = P / 3136;
        const int rem = P - b * 3136;
        const int hh  = rem / 56, ww = rem - (rem / 56) * 56;
        const int h   = hpar + 2 * hh;
        const int w   = wpar + 2 * ww;
        const int ih  = (h + 1) >> 1, jw = (w + 1) >> 1;
        const int nn  = b * 8 + route;         // reference reshape quirk
        const int bb  = nn & 3, cin = nn >> 2;
        const int ii = ih - (mytap >> 1);
        const int jj = jw - (mytap & 1);
        const bool valid = ((unsigned)ii < (unsigned)HIN) && ((unsigned)jj < (unsigned)WIN);
        const int iic = valid ? ii : 0, jjc = valid ? jj : 0;
        const uint32_t ssz = valid ? 16u : 0u;
        const char* shi = (const char*)(g_xh
            + (size_t)(((bb * HIN + iic) * WIN + jjc) * CIN + cin) * AIN);
        #pragma unroll
        for (int c = 0; c < 4; ++c) {
            const uint32_t cb  = (uint32_t)(mytap * 4 + c);
            const uint32_t dof = (uint32_t)m * 256 + ((cb << 4) ^ rx_m);
            cpa16(sbase + SM_A + dof, shi + c * 16, ssz);
        }
        cpa_commit();
    };

    // ---- mainloop constants: warp tile rows mb..mb+31 (of 128), cols nbase..+31
    const int mb    = (wid & 3) * 32;
    const int nbase = (wid >> 2) * 32;
    const int ar = lane & 15;
    const uint32_t rowA0 = (uint32_t)((mb + ar) * 256);
    const uint32_t rowA1 = (uint32_t)((mb + 16 + ar) * 256);
    const uint32_t a_kl  = (uint32_t)((lane >> 4) << 4);
    const uint32_t rxA   = (uint32_t)(ar & 7) << 4;
    const int brr = (lane & 7) + ((lane >> 4) << 3);
    uint32_t rowB[2];
    #pragma unroll
    for (int nt = 0; nt < 2; ++nt)
        rowB[nt] = (uint32_t)((nbase + nt * 16 + brr) * 256);
    const uint32_t b_kl = (uint32_t)(((lane >> 3) & 1) << 4);
    const uint32_t rxB  = (uint32_t)(lane & 7) << 4;

    // D-staging constants (store side)
    const int dg  = lane >> 2;
    const int dc2 = (lane & 3) * 2;
    const uint32_t dxor = (uint32_t)dg << 4;

    // prologue gather of tile 0
    gather(base);

    #pragma unroll 1
    for (int it = 0; it < cnt; ++it) {
        asm volatile("cp.async.wait_group 0;" ::: "memory");
        __syncthreads();   // sync #1: A(t) (and B on t=0) visible to all warps

        // ---- mainloop: 8 k-steps, single fp16 term, warp tile 32x32
        float d[2][4][4];
        #pragma unroll
        for (int mi = 0; mi < 2; ++mi)
            #pragma unroll
            for (int nq = 0; nq < 4; ++nq)
                #pragma unroll
                for (int j = 0; j < 4; ++j) d[mi][nq][j] = 0.f;

        {
            const uint32_t Ahi = sbase + SM_A;
            const uint32_t Bhi = sbase + SM_B;
            #pragma unroll
            for (int k0 = 0; k0 < 128; k0 += 16) {
                const uint32_t ka = ((uint32_t)(k0 * 2) + a_kl) ^ rxA;
                const uint32_t kb = ((uint32_t)(k0 * 2) + b_kl) ^ rxB;
                uint32_t ahi[2][4], bfr[4];
                ldm_x4(ahi[0], Ahi + rowA0 + ka);
                ldm_x4(ahi[1], Ahi + rowA1 + ka);
                #pragma unroll
                for (int nt = 0; nt < 2; ++nt) {
                    ldm_x4(bfr, Bhi + rowB[nt] + kb);
                    #pragma unroll
                    for (int mi = 0; mi < 2; ++mi) {
                        mma_f16(d[mi][nt * 2 + 0], ahi[mi], bfr + 0);
                        mma_f16(d[mi][nt * 2 + 1], ahi[mi], bfr + 2);
                    }
                }
            }
        }

        // ---- stage D as half2 into disjoint D region (128 rows x 256B)
        {
            char* Dp = smem + SM_D;
            #pragma unroll
            for (int mi = 0; mi < 2; ++mi) {
                #pragma unroll
                for (int nq = 0; nq < 4; ++nq) {
                    const int col = nbase + nq * 8 + dc2;
                    const int r0  = mb + mi * 16 + dg;
                    const uint32_t cbs = ((uint32_t)(col * 2)) ^ dxor;
                    *(uint32_t*)(Dp + (uint32_t)r0 * 256 + cbs)
                        = pack_h2(d[mi][nq][0], d[mi][nq][1]);
                    *(uint32_t*)(Dp + (uint32_t)(r0 + 8) * 256 + cbs)
                        = pack_h2(d[mi][nq][2], d[mi][nq][3]);
                }
            }
        }
        __syncthreads();   // sync #2: all D visible (also: all A reads done)

        // ---- load routing acc regs (one pixel per warp: p = wid, 0..15)
        float acc[8][4];
        {
            const char* Dp = smem + SM_D;
            #pragma unroll
            for (int i = 0; i < 8; ++i) {
                const int R = wid * 8 + i;                 // R&7 == i
                uint32_t off = (uint32_t)R * 256
                             + (((uint32_t)(lane * 8)) ^ ((uint32_t)i << 4));
                uint2 v = *(const uint2*)(Dp + off);
                float2 f0 = __half22float2(*(__half2*)&v.x);
                float2 f1 = __half22float2(*(__half2*)&v.y);
                acc[i][0] = f0.x; acc[i][1] = f0.y;
                acc[i][2] = f1.x; acc[i][3] = f1.y;
            }
        }

        // ---- hoisted gather: writes A only (disjoint from D) -> no sync.
        if (it + 1 < cnt) gather(base + it + 1);

        // ---- routing math (registers + shuffles only)
        {
            const float4 bs = __ldg((const float4*)bias + lane);
            float logits[8];
            float a0, a1, a2, a3;

            // iteration 0: softmax(0) == 0.125 exactly
            {
                float p0 = bs.x, p1 = bs.y, p2 = bs.z, p3 = bs.w;
                float s0 = 0.f, s1 = 0.f, s2 = 0.f, s3 = 0.f;
                #pragma unroll
                for (int i = 0; i < 8; ++i) {
                    s0 += acc[i][0]; s1 += acc[i][1];
                    s2 += acc[i][2]; s3 += acc[i][3];
                }
                p0 = fmaf(0.125f, s0, p0); p1 = fmaf(0.125f, s1, p1);
                p2 = fmaf(0.125f, s2, p2); p3 = fmaf(0.125f, s3, p3);
                float sq = p0 * p0 + p1 * p1 + p2 * p2 + p3 * p3;
                sq += __shfl_xor_sync(0xffffffffu, sq, 1);
                sq += __shfl_xor_sync(0xffffffffu, sq, 2);
                float scale = __fdividef(sq, 1.0f + sq) * rsqrtf(sq + 1e-9f);
                a0 = p0 * scale; a1 = p1 * scale; a2 = p2 * scale; a3 = p3 * scale;
                #pragma unroll
                for (int i = 0; i < 8; ++i) {
                    float dd = acc[i][0] * a0 + acc[i][1] * a1
                             + acc[i][2] * a2 + acc[i][3] * a3;
                    dd += __shfl_xor_sync(0xffffffffu, dd, 1);
                    dd += __shfl_xor_sync(0xffffffffu, dd, 2);
                    logits[i] = dd;
                }
            }

            // iterations 1,2: softmax without max-sub (|logits| small)
            #pragma unroll
            for (int itr = 1; itr < 3; ++itr) {
                float r[8];
                #pragma unroll
                for (int i = 0; i < 8; ++i) {
                    float e = __expf(logits[i]);
                    float ss = e;
                    ss += __shfl_xor_sync(0xffffffffu, ss, 4);
                    ss += __shfl_xor_sync(0xffffffffu, ss, 8);
                    ss += __shfl_xor_sync(0xffffffffu, ss, 16);
                    r[i] = __fdividef(e, ss);
                }
                float p0 = bs.x, p1 = bs.y, p2 = bs.z, p3 = bs.w;
                #pragma unroll
                for (int i = 0; i < 8; ++i) {
                    p0 = fmaf(r[i], acc[i][0], p0);
                    p1 = fmaf(r[i], acc[i][1], p1);
                    p2 = fmaf(r[i], acc[i][2], p2);
                    p3 = fmaf(r[i], acc[i][3], p3);
                }
                float sq = p0 * p0 + p1 * p1 + p2 * p2 + p3 * p3;
                sq += __shfl_xor_sync(0xffffffffu, sq, 1);
                sq += __shfl_xor_sync(0xffffffffu, sq, 2);
                float scale = __fdividef(sq, 1.0f + sq) * rsqrtf(sq + 1e-9f);
                a0 = p0 * scale; a1 = p1 * scale; a2 = p2 * scale; a3 = p3 * scale;

                if (itr == 1) {
                    #pragma unroll
                    for (int i = 0; i < 8; ++i) {
                        float dd = acc[i][0] * a0 + acc[i][1] * a1
                                 + acc[i][2] * a2 + acc[i][3] * a3;
                        dd += __shfl_xor_sync(0xffffffffu, dd, 1);
                        dd += __shfl_xor_sync(0xffffffffu, dd, 2);
                        logits[i] += dd;
                    }
                }
            }

            const int P   = (base + it) * 16 + wid;
            const int b   = P / 3136;
            const int rem = P - b * 3136;
            const int hh  = rem / 56, ww = rem - (rem / 56) * 56;
            const int h   = hpar + 2 * hh;
            const int w   = wpar + 2 * ww;
            ((float4*)out)[(size_t)((b * HP + h) * WP + w) * 32 + lane]
                = make_float4(a0, a1, a2, a3);
        }
    }
}

extern "C" void kernel_launch(void* const* d_in, const int* in_sizes, int n_in,
                              void* d_out, int out_size) {
    const float* x = nullptr;
    const float* W = nullptr;
    const float* bias = nullptr;
    for (int i = 0; i < n_in; ++i) {
        if (in_sizes[i] == XN)                    x    = (const float*)d_in[i];
        else if (in_sizes[i] == 4 * 4 * 128 * 32) W    = (const float*)d_in[i];
        else if (in_sizes[i] == 128)              bias = (const float*)d_in[i];
    }
    float* out = (float*)d_out;

    cudaFuncSetAttribute(deconv_caps_pers_kernel,
                         cudaFuncAttributeMaxDynamicSharedMemorySize, SMEM_TOTAL);

    prep_kernel<<<(XN / 8 + 255) / 256, 256>>>(W, x);

    dim3 grid(NBLK, 4);
    deconv_caps_pers_kernel<<<grid, 512, SMEM_TOTAL>>>(bias, out);
}

// round 17
// speedup vs baseline: 1.0231x; 1.0231x over previous
#include <cuda_runtime.h>
#include <cuda_fp16.h>
#include <cstdint>

// DeconvCapsuleLayer, round 17: warp-specialized producer/consumer.
//   - 384 threads: warps 0..7 = GEMM (gather + fp16 mma.sync + D-store),
//                  warps 8..11 = routing (2 pixels each, register routing).
//   - D double-buffered (2 x 16KB half2); named-barrier full/empty protocol.
//   - Routing (~60% of instructions) now overlaps GEMM by construction.
// smem 80KB -> 2 blocks/SM; launch_bounds(384,2) -> 80-reg cap (= round 15).
// Numerics identical to rounds 13/15 (rel_err 4.31e-4).
//
// Reference quirk reproduced: route i of output batch b uses input
// (bb, cin) = ((8b+i)&3, (8b+i)>>2).

namespace {
constexpr int HIN = 56, WIN = 56, CIN = 8, AIN = 32;
constexpr int HP = 112, WP = 112;
constexpr int XN = 4 * 56 * 56 * 8 * 32;     // elements in x
constexpr int BN = 4 * 128 * 128;            // elements in B (hi only)
// SMEM: B 32KB | A 16KB | D0 16KB | D1 16KB
constexpr int SM_B  = 0;
constexpr int SM_A  = 32768;
constexpr int SM_D0 = 49152;
constexpr int SMEM_TOTAL = 81920;
constexpr int NBLK = 74;                     // blocks per class (296 = 148*2)
// named barrier ids (never use __syncthreads in the loop)
constexpr int BAR_A  = 1;   // GEMM group, 256
constexpr int BAR_A2 = 2;   // GEMM group, 256
constexpr int BAR_E0 = 3;   // empty buf0, 384
constexpr int BAR_E1 = 4;   // empty buf1, 384
constexpr int BAR_F0 = 5;   // full  buf0, 384
constexpr int BAR_F1 = 6;   // full  buf1, 384
}

__device__ __half g_B[BN];    // pre-swizzled B_hi: [cls][n(128)][k(128)]
__device__ __half g_xh[XN];   // fp16 hi of x

__global__ void __launch_bounds__(256)
prep_kernel(const float* __restrict__ W, const float* __restrict__ x) {
    int idx = blockIdx.x * blockDim.x + threadIdx.x;
    if (idx < XN / 8) {
        const float4* xs = (const float4*)x + idx * 2;
        float4 v0 = xs[0];
        float4 v1 = xs[1];
        __half2 h0 = __floats2half2_rn(v0.x, v0.y);
        __half2 h1 = __floats2half2_rn(v0.z, v0.w);
        __half2 h2 = __floats2half2_rn(v1.x, v1.y);
        __half2 h3 = __floats2half2_rn(v1.z, v1.w);
        ((uint4*)g_xh)[idx] = make_uint4(*(uint32_t*)&h0, *(uint32_t*)&h1,
                                         *(uint32_t*)&h2, *(uint32_t*)&h3);
    }
    if (idx < BN) {
        int k   = idx & 127;
        int n   = (idx >> 7) & 127;
        int cls = idx >> 14;
        int t = k >> 5, ain = k & 31;
        int hpar = cls >> 1, wpar = cls & 1;
        int p = (1 - hpar) + 2 * (t >> 1);
        int q = (1 - wpar) + 2 * (t & 1);
        float wv = W[((p * 4 + q) * 128 + n) * AIN + ain];
        uint32_t off = (uint32_t)(n * 256)
                     + (((uint32_t)(k * 2)) ^ ((uint32_t)(n & 7) << 4));
        *(__half*)((char*)g_B + (((size_t)cls) << 15) + off) = __float2half_rn(wv);
    }
}

// ---------------- PTX helpers ----------------
__device__ __forceinline__ void cpa16(uint32_t dst, const void* src, uint32_t srcsize) {
    asm volatile("cp.async.cg.shared.global [%0], [%1], 16, %2;"
                 :: "r"(dst), "l"(src), "r"(srcsize) : "memory");
}
__device__ __forceinline__ void cpa_commit() {
    asm volatile("cp.async.commit_group;" ::: "memory");
}
__device__ __forceinline__ void ldm_x4(uint32_t* r, uint32_t addr) {
    asm volatile("ldmatrix.sync.aligned.m8n8.x4.shared.b16 {%0,%1,%2,%3}, [%4];"
                 : "=r"(r[0]), "=r"(r[1]), "=r"(r[2]), "=r"(r[3]) : "r"(addr));
}
__device__ __forceinline__ void mma_f16(float* d, const uint32_t* a, const uint32_t* b) {
    asm volatile("mma.sync.aligned.m16n8k16.row.col.f32.f16.f16.f32 "
                 "{%0,%1,%2,%3}, {%4,%5,%6,%7}, {%8,%9}, {%0,%1,%2,%3};"
                 : "+f"(d[0]), "+f"(d[1]), "+f"(d[2]), "+f"(d[3])
                 : "r"(a[0]), "r"(a[1]), "r"(a[2]), "r"(a[3]), "r"(b[0]), "r"(b[1]));
}
__device__ __forceinline__ uint32_t pack_h2(float a, float b) {
    __half2 h = __floats2half2_rn(a, b);
    return *(uint32_t*)&h;
}
__device__ __forceinline__ void bar_sync(int id, int cnt) {
    asm volatile("bar.sync %0, %1;" :: "r"(id), "r"(cnt) : "memory");
}
__device__ __forceinline__ void bar_arrive(int id, int cnt) {
    asm volatile("bar.arrive %0, %1;" :: "r"(id), "r"(cnt) : "memory");
}

__global__ void __launch_bounds__(384, 2)
deconv_caps_ws_kernel(const float* __restrict__ bias,
                      float* __restrict__ out)
{
    extern __shared__ char smem[];
    const uint32_t sbase = (uint32_t)__cvta_generic_to_shared(smem);
    const int tid  = threadIdx.x;
    const int lane = tid & 31;
    const int wid  = tid >> 5;               // 0..11
    const int cls  = blockIdx.y;
    const int blk  = blockIdx.x;
    const int hpar = cls >> 1, wpar = cls & 1;

    // 1568 tiles/class over 74 blocks -> first 14 get 22, rest 21
    const int base = blk * 21 + (blk < 14 ? blk : 14);
    const int cnt  = 21 + (blk < 14 ? 1 : 0);

    if (wid < 8) {
        // ================= GEMM warps (threads 0..255) =================
        // ---- B copy (pre-swizzled, 32KB)
        {
            const char* Bsrc = (const char*)g_B + ((size_t)cls << 15);
            #pragma unroll
            for (int i = 0; i < 8; ++i) {
                uint32_t o = (uint32_t)(tid + 256 * i) * 16;
                cpa16(sbase + SM_B + o, Bsrc + o, 16);
            }
            cpa_commit();
        }

        // gather constants: row m = tid>>2 (0..63), tap = tid&3
        const int m = tid >> 2, mytap = tid & 3;
        const int mypix = m >> 3, route = m & 7;
        const uint32_t rx_m = (uint32_t)(m & 7) << 4;

        auto gather = [&](int T) {
            const int P   = T * 8 + mypix;
            const int b   = P / 3136;
            const int rem = P - b * 3136;
            const int hh  = rem / 56, ww = rem - (rem / 56) * 56;
            const int h   = hpar + 2 * hh;
            const int w   = wpar + 2 * ww;
            const int ih  = (h + 1) >> 1, jw = (w + 1) >> 1;
            const int nn  = b * 8 + route;     // reference reshape quirk
            const int bb  = nn & 3, cin = nn >> 2;
            const int ii = ih - (mytap >> 1);
            const int jj = jw - (mytap & 1);
            const bool valid = ((unsigned)ii < (unsigned)HIN) && ((unsigned)jj < (unsigned)WIN);
            const int iic = valid ? ii : 0, jjc = valid ? jj : 0;
            const uint32_t ssz = valid ? 16u : 0u;
            const char* shi = (const char*)(g_xh
                + (size_t)(((bb * HIN + iic) * WIN + jjc) * CIN + cin) * AIN);
            #pragma unroll
            for (int c = 0; c < 4; ++c) {
                const uint32_t cb  = (uint32_t)(mytap * 4 + c);
                const uint32_t dof = (uint32_t)m * 256 + ((cb << 4) ^ rx_m);
                cpa16(sbase + SM_A + dof, shi + c * 16, ssz);
            }
            cpa_commit();
        };

        // mainloop constants: warp tile rows mb..mb+31 (of 64), cols nbase..+31
        const int mb    = (wid & 1) * 32;
        const int nbase = (wid >> 1) * 32;
        const int ar = lane & 15;
        const uint32_t rowA0 = (uint32_t)((mb + ar) * 256);
        const uint32_t rowA1 = (uint32_t)((mb + 16 + ar) * 256);
        const uint32_t a_kl  = (uint32_t)((lane >> 4) << 4);
        const uint32_t rxA   = (uint32_t)(ar & 7) << 4;
        const int brr = (lane & 7) + ((lane >> 4) << 3);
        uint32_t rowB[2];
        #pragma unroll
        for (int nt = 0; nt < 2; ++nt)
            rowB[nt] = (uint32_t)((nbase + nt * 16 + brr) * 256);
        const uint32_t b_kl = (uint32_t)(((lane >> 3) & 1) << 4);
        const uint32_t rxB  = (uint32_t)(lane & 7) << 4;

        const int dg  = lane >> 2;
        const int dc2 = (lane & 3) * 2;
        const uint32_t dxor = (uint32_t)dg << 4;

        gather(base);

        #pragma unroll 1
        for (int it = 0; it < cnt; ++it) {
            asm volatile("cp.async.wait_group 0;" ::: "memory");
            bar_sync(BAR_A, 256);            // A(t) (and B on t=0) visible

            float d[2][4][4];
            #pragma unroll
            for (int mi = 0; mi < 2; ++mi)
                #pragma unroll
                for (int nq = 0; nq < 4; ++nq)
                    #pragma unroll
                    for (int j = 0; j < 4; ++j) d[mi][nq][j] = 0.f;

            {
                const uint32_t Ahi = sbase + SM_A;
                const uint32_t Bhi = sbase + SM_B;
                #pragma unroll
                for (int k0 = 0; k0 < 128; k0 += 16) {
                    const uint32_t ka = ((uint32_t)(k0 * 2) + a_kl) ^ rxA;
                    const uint32_t kb = ((uint32_t)(k0 * 2) + b_kl) ^ rxB;
                    uint32_t ahi[2][4], bfr[4];
                    ldm_x4(ahi[0], Ahi + rowA0 + ka);
                    ldm_x4(ahi[1], Ahi + rowA1 + ka);
                    #pragma unroll
                    for (int nt = 0; nt < 2; ++nt) {
                        ldm_x4(bfr, Bhi + rowB[nt] + kb);
                        #pragma unroll
                        for (int mi = 0; mi < 2; ++mi) {
                            mma_f16(d[mi][nt * 2 + 0], ahi[mi], bfr + 0);
                            mma_f16(d[mi][nt * 2 + 1], ahi[mi], bfr + 2);
                        }
                    }
                }
            }
            bar_sync(BAR_A2, 256);           // all GEMM warps done reading A(t)

            if (it + 1 < cnt) gather(base + it + 1);

            // wait consumer done with this D buffer, then store + publish
            const int bsel = it & 1;
            bar_sync(BAR_E0 + bsel, 384);
            {
                char* Dp = smem + SM_D0 + (bsel << 14);
                #pragma unroll
                for (int mi = 0; mi < 2; ++mi) {
                    #pragma unroll
                    for (int nq = 0; nq < 4; ++nq) {
                        const int col = nbase + nq * 8 + dc2;
                        const int r0  = mb + mi * 16 + dg;
                        const uint32_t cbs = ((uint32_t)(col * 2)) ^ dxor;
                        *(uint32_t*)(Dp + (uint32_t)r0 * 256 + cbs)
                            = pack_h2(d[mi][nq][0], d[mi][nq][1]);
                        *(uint32_t*)(Dp + (uint32_t)(r0 + 8) * 256 + cbs)
                            = pack_h2(d[mi][nq][2], d[mi][nq][3]);
                    }
                }
            }
            asm volatile("membar.cta;" ::: "memory");
            bar_arrive(BAR_F0 + bsel, 384);
        }
    } else {
        // ================= Routing warps (wid 8..11) =================
        const int rw = wid - 8;              // 0..3 -> pixels 2rw, 2rw+1
        const float4 bs = __ldg((const float4*)bias + lane);

        // pre-arm both empty barriers
        bar_arrive(BAR_E0, 384);
        bar_arrive(BAR_E1, 384);

        #pragma unroll 1
        for (int it = 0; it < cnt; ++it) {
            const int bsel = it & 1;
            bar_sync(BAR_F0 + bsel, 384);    // D(t) published
            const char* Dp = smem + SM_D0 + (bsel << 14);

            #pragma unroll 1
            for (int j = 0; j < 2; ++j) {
                const int p = rw * 2 + j;
                float acc[8][4];
                #pragma unroll
                for (int i = 0; i < 8; ++i) {
                    const int R = p * 8 + i;             // R&7 == i
                    uint32_t off = (uint32_t)R * 256
                                 + (((uint32_t)(lane * 8)) ^ ((uint32_t)i << 4));
                    uint2 v = *(const uint2*)(Dp + off);
                    float2 f0 = __half22float2(*(__half2*)&v.x);
                    float2 f1 = __half22float2(*(__half2*)&v.y);
                    acc[i][0] = f0.x; acc[i][1] = f0.y;
                    acc[i][2] = f1.x; acc[i][3] = f1.y;
                }

                float logits[8];
                float a0, a1, a2, a3;

                // iteration 0: softmax(0) == 0.125 exactly
                {
                    float p0 = bs.x, p1 = bs.y, p2 = bs.z, p3 = bs.w;
                    float s0 = 0.f, s1 = 0.f, s2 = 0.f, s3 = 0.f;
                    #pragma unroll
                    for (int i = 0; i < 8; ++i) {
                        s0 += acc[i][0]; s1 += acc[i][1];
                        s2 += acc[i][2]; s3 += acc[i][3];
                    }
                    p0 = fmaf(0.125f, s0, p0); p1 = fmaf(0.125f, s1, p1);
                    p2 = fmaf(0.125f, s2, p2); p3 = fmaf(0.125f, s3, p3);
                    float sq = p0 * p0 + p1 * p1 + p2 * p2 + p3 * p3;
                    sq += __shfl_xor_sync(0xffffffffu, sq, 1);
                    sq += __shfl_xor_sync(0xffffffffu, sq, 2);
                    float scale = __fdividef(sq, 1.0f + sq) * rsqrtf(sq + 1e-9f);
                    a0 = p0 * scale; a1 = p1 * scale; a2 = p2 * scale; a3 = p3 * scale;
                    #pragma unroll
                    for (int i = 0; i < 8; ++i) {
                        float dd = acc[i][0] * a0 + acc[i][1] * a1
                                 + acc[i][2] * a2 + acc[i][3] * a3;
                        dd += __shfl_xor_sync(0xffffffffu, dd, 1);
                        dd += __shfl_xor_sync(0xffffffffu, dd, 2);
                        logits[i] = dd;
                    }
                }

                // iterations 1,2
                #pragma unroll
                for (int itr = 1; itr < 3; ++itr) {
                    float r[8];
                    #pragma unroll
                    for (int i = 0; i < 8; ++i) {
                        float e = __expf(logits[i]);
                        float ss = e;
                        ss += __shfl_xor_sync(0xffffffffu, ss, 4);
                        ss += __shfl_xor_sync(0xffffffffu, ss, 8);
                        ss += __shfl_xor_sync(0xffffffffu, ss, 16);
                        r[i] = __fdividef(e, ss);
                    }
                    float p0 = bs.x, p1 = bs.y, p2 = bs.z, p3 = bs.w;
                    #pragma unroll
                    for (int i = 0; i < 8; ++i) {
                        p0 = fmaf(r[i], acc[i][0], p0);
                        p1 = fmaf(r[i], acc[i][1], p1);
                        p2 = fmaf(r[i], acc[i][2], p2);
                        p3 = fmaf(r[i], acc[i][3], p3);
                    }
                    float sq = p0 * p0 + p1 * p1 + p2 * p2 + p3 * p3;
                    sq += __shfl_xor_sync(0xffffffffu, sq, 1);
                    sq += __shfl_xor_sync(0xffffffffu, sq, 2);
                    float scale = __fdividef(sq, 1.0f + sq) * rsqrtf(sq + 1e-9f);
                    a0 = p0 * scale; a1 = p1 * scale; a2 = p2 * scale; a3 = p3 * scale;

                    if (itr == 1) {
                        #pragma unroll
                        for (int i = 0; i < 8; ++i) {
                            float dd = acc[i][0] * a0 + acc[i][1] * a1
                                     + acc[i][2] * a2 + acc[i][3] * a3;
                            dd += __shfl_xor_sync(0xffffffffu, dd, 1);
                            dd += __shfl_xor_sync(0xffffffffu, dd, 2);
                            logits[i] += dd;
                        }
                    }
                }

                const int P   = (base + it) * 8 + p;
                const int b   = P / 3136;
                const int rem = P - b * 3136;
                const int hh  = rem / 56, ww = rem - (rem / 56) * 56;
                const int h   = hpar + 2 * hh;
                const int w   = wpar + 2 * ww;
                ((float4*)out)[(size_t)((b * HP + h) * WP + w) * 32 + lane]
                    = make_float4(a0, a1, a2, a3);
            }

            // all reads of this D buffer are consumed (values used above)
            bar_arrive(BAR_E0 + bsel, 384);
        }
    }
}

extern "C" void kernel_launch(void* const* d_in, const int* in_sizes, int n_in,
                              void* d_out, int out_size) {
    const float* x = nullptr;
    const float* W = nullptr;
    const float* bias = nullptr;
    for (int i = 0; i < n_in; ++i) {
        if (in_sizes[i] == XN)                    x    = (const float*)d_in[i];
        else if (in_sizes[i] == 4 * 4 * 128 * 32) W    = (const float*)d_in[i];
        else if (in_sizes[i] == 128)              bias = (const float*)d_in[i];
    }
    float* out = (float*)d_out;

    cudaFuncSetAttribute(deconv_caps_ws_kernel,
                         cudaFuncAttributeMaxDynamicSharedMemorySize, SMEM_TOTAL);

    prep_kernel<<<(XN / 8 + 255) / 256, 256>>>(W, x);

    dim3 grid(NBLK, 4);
    deconv_caps_ws_kernel<<<grid, 384, SMEM_TOTAL>>>(bias, out);
}